// round 1
// baseline (speedup 1.0000x reference)
#include <cuda_runtime.h>

// NeuralODE: adaptive Tsit5, B=4096 trajectories, D=64 state, MLP 64->32->32->64.
// One warp per trajectory; weights transposed in shared; early-exit inner loop
// (bit-equivalent to the reference's masked 64-iteration scan).

#define NB    4096
#define ND    64
#define NH    32
#define NTRAJ 11
#define MAXI  64
#define WPB   8
#define NTHR  (WPB * 32)
#define NBLK  (NB / WPB)
#define OUT_TRAJ (NB * NTRAJ * ND)

// Tsit5 tableau (float32, matching JAX weak-typed constants)
#define A21 0.161f
#define A31 (-0.008480655492356989f)
#define A32 0.335480655492357f
#define A41 2.8971530571054935f
#define A42 (-6.359448489975075f)
#define A43 4.3622954328695815f
#define A51 5.325864828439257f
#define A52 (-11.748883564062828f)
#define A53 7.4955393428898365f
#define A54 (-0.09249506636175525f)
#define A61 5.86145544294642f
#define A62 (-12.92096931784711f)
#define A63 8.159367898576159f
#define A64 (-0.071584973281401f)
#define A65 (-0.028269050394068383f)
#define CB1 0.09646076681806523f
#define CB2 0.01f
#define CB3 0.4798896504144996f
#define CB4 1.379008574103742f
#define CB5 (-3.290069515436081f)
#define CB6 2.324710524099774f
#define CE1 (-0.00178001105222577714f)
#define CE2 (-0.0008164344596567469f)
#define CE3 0.007880878010261995f
#define CE4 (-0.1447110071732629f)
#define CE5 0.5823571654525552f
#define CE6 (-0.45808210592918697f)
#define CE7 0.015151515151515152f

#define RTOL 1e-3f
#define ATOL 1e-6f
#define DT0  1e-3f

__device__ int g_nsum;

__device__ __forceinline__ float softplus_f(float x) {
    // jax.nn.softplus == logaddexp(x, 0) == max(x,0) + log1p(exp(-|x|))
    return fmaxf(x, 0.0f) + log1pf(expf(-fabsf(x)));
}

struct F2 { float a, b; };

// One MLP eval. Stage input (a0 = comp[lane], a1 = comp[lane+32]) in registers.
// Weights transposed in smem: conflict-free per-lane columns, broadcast stage reads.
__device__ __forceinline__ F2 mlp_eval(
    const float* __restrict__ sW1, const float* __restrict__ sW2,
    const float* __restrict__ sW3, const float* __restrict__ sb1,
    const float* __restrict__ sb2, const float* __restrict__ sb3,
    float* __restrict__ ysw, float* __restrict__ hsw,
    int lane, float a0, float a1)
{
    __syncwarp();
    ysw[lane]      = a0;
    ysw[lane + 32] = a1;
    __syncwarp();
    float acc = sb1[lane];
#pragma unroll
    for (int j = 0; j < ND; j++)
        acc = fmaf(sW1[j * NH + lane], ysw[j], acc);
    acc = softplus_f(acc);
    __syncwarp();
    hsw[lane] = acc;
    __syncwarp();
    float acc2 = sb2[lane];
#pragma unroll
    for (int j = 0; j < NH; j++)
        acc2 = fmaf(sW2[j * NH + lane], hsw[j], acc2);
    acc2 = softplus_f(acc2);
    __syncwarp();
    hsw[lane] = acc2;
    __syncwarp();
    float o0 = sb3[lane], o1 = sb3[lane + 32];
#pragma unroll
    for (int i = 0; i < NH; i++) {
        float hv = hsw[i];
        o0 = fmaf(sW3[i * ND + lane],      hv, o0);
        o1 = fmaf(sW3[i * ND + lane + 32], hv, o1);
    }
    F2 r; r.a = o0; r.b = o1; return r;
}

__global__ void __launch_bounds__(NTHR) ode_zero_kernel() { g_nsum = 0; }

__global__ void __launch_bounds__(NTHR) ode_kernel(
    const float* __restrict__ x0s,
    const float* __restrict__ W1, const float* __restrict__ b1,
    const float* __restrict__ W2, const float* __restrict__ b2,
    const float* __restrict__ W3, const float* __restrict__ b3,
    const int*   __restrict__ Tptr,
    float* __restrict__ out)
{
    __shared__ float sW1[ND * NH];   // sW1[j*32+i] = W1[i][j]
    __shared__ float sW2[NH * NH];   // sW2[j*32+i] = W2[i][j]
    __shared__ float sW3[NH * ND];   // sW3[i*64+c] = W3[c][i]
    __shared__ float sb1[NH], sb2[NH], sb3[ND];
    __shared__ float ys[WPB][ND];
    __shared__ float hs[WPB][NH];

    const int tid = threadIdx.x;
    for (int idx = tid; idx < ND * NH; idx += NTHR) {
        int i = idx / ND, j = idx % ND;
        sW1[j * NH + i] = W1[idx];
    }
    for (int idx = tid; idx < NH * NH; idx += NTHR) {
        int i = idx / NH, j = idx % NH;
        sW2[j * NH + i] = W2[idx];
    }
    for (int idx = tid; idx < ND * NH; idx += NTHR) {
        int c = idx / NH, i = idx % NH;
        sW3[i * ND + c] = W3[idx];
    }
    if (tid < NH) { sb1[tid] = b1[tid]; sb2[tid] = b2[tid]; }
    if (tid < ND) sb3[tid] = b3[tid];
    __syncthreads();

    const int w    = tid >> 5;
    const int lane = tid & 31;
    const int traj = blockIdx.x * WPB + w;
    float* ysw = ys[w];
    float* hsw = hs[w];

    float y0 = x0s[traj * ND + lane];
    float y1 = x0s[traj * ND + 32 + lane];
    float* otraj = out + (size_t)traj * (NTRAJ * ND);
    otraj[lane]      = y0;
    otraj[32 + lane] = y1;

    const float delta = (float)(*Tptr) * 0.1f;   // linspace step; exact for T=10
    float t  = 0.0f;
    float dt = DT0;
    int   n  = 0;

    for (int s = 1; s < NTRAJ; s++) {
        float t_target = delta * (float)s;
        for (int it = 0; it < MAXI; it++) {
            float remaining = t_target - t;
            if (remaining <= 1e-12f) break;          // == masked no-op iterations
            float h = fminf(dt, fmaxf(remaining, 0.0f));

            F2 k1 = mlp_eval(sW1, sW2, sW3, sb1, sb2, sb3, ysw, hsw, lane, y0, y1);
            F2 k2 = mlp_eval(sW1, sW2, sW3, sb1, sb2, sb3, ysw, hsw, lane,
                             y0 + h * (A21 * k1.a),
                             y1 + h * (A21 * k1.b));
            F2 k3 = mlp_eval(sW1, sW2, sW3, sb1, sb2, sb3, ysw, hsw, lane,
                             y0 + h * (A31 * k1.a + A32 * k2.a),
                             y1 + h * (A31 * k1.b + A32 * k2.b));
            F2 k4 = mlp_eval(sW1, sW2, sW3, sb1, sb2, sb3, ysw, hsw, lane,
                             y0 + h * (A41 * k1.a + A42 * k2.a + A43 * k3.a),
                             y1 + h * (A41 * k1.b + A42 * k2.b + A43 * k3.b));
            F2 k5 = mlp_eval(sW1, sW2, sW3, sb1, sb2, sb3, ysw, hsw, lane,
                             y0 + h * (A51 * k1.a + A52 * k2.a + A53 * k3.a + A54 * k4.a),
                             y1 + h * (A51 * k1.b + A52 * k2.b + A53 * k3.b + A54 * k4.b));
            F2 k6 = mlp_eval(sW1, sW2, sW3, sb1, sb2, sb3, ysw, hsw, lane,
                             y0 + h * (A61 * k1.a + A62 * k2.a + A63 * k3.a + A64 * k4.a + A65 * k5.a),
                             y1 + h * (A61 * k1.b + A62 * k2.b + A63 * k3.b + A64 * k4.b + A65 * k5.b));

            float y5a = y0 + h * (CB1 * k1.a + CB2 * k2.a + CB3 * k3.a +
                                  CB4 * k4.a + CB5 * k5.a + CB6 * k6.a);
            float y5b = y1 + h * (CB1 * k1.b + CB2 * k2.b + CB3 * k3.b +
                                  CB4 * k4.b + CB5 * k5.b + CB6 * k6.b);

            F2 k7 = mlp_eval(sW1, sW2, sW3, sb1, sb2, sb3, ysw, hsw, lane, y5a, y5b);

            float ea = h * (CE1 * k1.a + CE2 * k2.a + CE3 * k3.a + CE4 * k4.a +
                            CE5 * k5.a + CE6 * k6.a + CE7 * k7.a);
            float eb = h * (CE1 * k1.b + CE2 * k2.b + CE3 * k3.b + CE4 * k4.b +
                            CE5 * k5.b + CE6 * k6.b + CE7 * k7.b);

            float sa  = ATOL + RTOL * fmaxf(fabsf(y0), fabsf(y5a));
            float sb_ = ATOL + RTOL * fmaxf(fabsf(y1), fabsf(y5b));
            float ra = ea / sa, rb = eb / sb_;
            float ss = ra * ra + rb * rb;
#pragma unroll
            for (int off = 16; off > 0; off >>= 1)
                ss += __shfl_xor_sync(0xffffffffu, ss, off);
            float enorm = fmaxf(sqrtf(ss * (1.0f / 64.0f)), 1e-10f);

            bool  accept = (enorm <= 1.0f);
            float fac = fminf(fmaxf(0.9f * powf(enorm, -0.2f), 0.1f), 5.0f);
            if (accept) { t = t + h; y0 = y5a; y1 = y5b; }
            dt = fmaxf(h * fac, 1e-8f);
            n += 1;
        }
        otraj[s * ND + lane]      = y0;
        otraj[s * ND + 32 + lane] = y1;
    }

    if (lane == 0) atomicAdd(&g_nsum, n);
}

__global__ void ode_write_n(float* __restrict__ out, int idx) {
    out[idx] = (float)g_nsum;
}

extern "C" void kernel_launch(void* const* d_in, const int* in_sizes, int n_in,
                              void* d_out, int out_size) {
    const float* x0s = (const float*)d_in[0];
    const float* W1  = (const float*)d_in[1];
    const float* b1  = (const float*)d_in[2];
    const float* W2  = (const float*)d_in[3];
    const float* b2  = (const float*)d_in[4];
    const float* W3  = (const float*)d_in[5];
    const float* b3  = (const float*)d_in[6];
    const int*   T   = (const int*)d_in[7];   // little-endian: safe for int32/int64
    float* out = (float*)d_out;

    ode_zero_kernel<<<1, 1>>>();
    ode_kernel<<<NBLK, NTHR>>>(x0s, W1, b1, W2, b2, W3, b3, T, out);
    if (out_size > OUT_TRAJ)
        ode_write_n<<<1, 1>>>(out, OUT_TRAJ);   // sum(ns) as float32 tail element
}

// round 7
// speedup vs baseline: 1.1040x; 1.1040x over previous
#include <cuda_runtime.h>

// NeuralODE adaptive Tsit5. One warp per trajectory; ALL weights in registers
// (W1 row + W2 row + two W3 rows per lane = 160 regs); stage-vector broadcasts
// via warp shuffle — zero shared memory in the hot loop. FSAL: k1 reused from
// previous k7 (bit-exact: f deterministic, y unchanged on reject).

#define NB    4096
#define ND    64
#define NH    32
#define NTRAJ 11
#define MAXI  64
#define NTHR  128
#define WPB   (NTHR / 32)
#define NBLK  (NB / WPB)
#define OUT_TRAJ (NB * NTRAJ * ND)
#define FULLM 0xffffffffu

#define A21 0.161f
#define A31 (-0.008480655492356989f)
#define A32 0.335480655492357f
#define A41 2.8971530571054935f
#define A42 (-6.359448489975075f)
#define A43 4.3622954328695815f
#define A51 5.325864828439257f
#define A52 (-11.748883564062828f)
#define A53 7.4955393428898365f
#define A54 (-0.09249506636175525f)
#define A61 5.86145544294642f
#define A62 (-12.92096931784711f)
#define A63 8.159367898576159f
#define A64 (-0.071584973281401f)
#define A65 (-0.028269050394068383f)
#define CB1 0.09646076681806523f
#define CB2 0.01f
#define CB3 0.4798896504144996f
#define CB4 1.379008574103742f
#define CB5 (-3.290069515436081f)
#define CB6 2.324710524099774f
#define CE1 (-0.00178001105222577714f)
#define CE2 (-0.0008164344596567469f)
#define CE3 0.007880878010261995f
#define CE4 (-0.1447110071732629f)
#define CE5 0.5823571654525552f
#define CE6 (-0.45808210592918697f)
#define CE7 0.015151515151515152f

#define RTOL 1e-3f
#define ATOL 1e-6f
#define DT0  1e-3f

__device__ int g_nsum;

__device__ __forceinline__ float softplus_f(float x) {
    return fmaxf(x, 0.0f) + log1pf(expf(-fabsf(x)));
}

struct F2 { float a, b; };

// MLP eval, fully register-resident. a0 = y[lane], a1 = y[lane+32].
__device__ __forceinline__ F2 mlp(
    const float (&w1)[ND], const float (&w2)[NH],
    const float (&w3a)[NH], const float (&w3b)[NH],
    float b1r, float b2r, float b3a, float b3b,
    float a0, float a1)
{
    // layer 1: 64-input dot, 4 accumulators for ILP
    float s0 = 0.f, s1 = 0.f, s2 = 0.f, s3 = 0.f;
#pragma unroll
    for (int j = 0; j < 32; j += 4) {
        s0 = fmaf(w1[j],     __shfl_sync(FULLM, a0, j),     s0);
        s1 = fmaf(w1[j + 1], __shfl_sync(FULLM, a0, j + 1), s1);
        s2 = fmaf(w1[j + 2], __shfl_sync(FULLM, a0, j + 2), s2);
        s3 = fmaf(w1[j + 3], __shfl_sync(FULLM, a0, j + 3), s3);
    }
#pragma unroll
    for (int j = 0; j < 32; j += 4) {
        s0 = fmaf(w1[32 + j],     __shfl_sync(FULLM, a1, j),     s0);
        s1 = fmaf(w1[32 + j + 1], __shfl_sync(FULLM, a1, j + 1), s1);
        s2 = fmaf(w1[32 + j + 2], __shfl_sync(FULLM, a1, j + 2), s2);
        s3 = fmaf(w1[32 + j + 3], __shfl_sync(FULLM, a1, j + 3), s3);
    }
    float h1 = softplus_f(b1r + ((s0 + s1) + (s2 + s3)));

    // layer 2: 32-input dot
    float t0 = 0.f, t1 = 0.f, t2 = 0.f, t3 = 0.f;
#pragma unroll
    for (int j = 0; j < 32; j += 4) {
        t0 = fmaf(w2[j],     __shfl_sync(FULLM, h1, j),     t0);
        t1 = fmaf(w2[j + 1], __shfl_sync(FULLM, h1, j + 1), t1);
        t2 = fmaf(w2[j + 2], __shfl_sync(FULLM, h1, j + 2), t2);
        t3 = fmaf(w2[j + 3], __shfl_sync(FULLM, h1, j + 3), t3);
    }
    float h2 = softplus_f(b2r + ((t0 + t1) + (t2 + t3)));

    // layer 3: two 32-input dots sharing broadcasts
    float p0 = 0.f, p1 = 0.f, q0 = 0.f, q1 = 0.f;
#pragma unroll
    for (int j = 0; j < 32; j += 2) {
        float v0 = __shfl_sync(FULLM, h2, j);
        float v1 = __shfl_sync(FULLM, h2, j + 1);
        p0 = fmaf(w3a[j],     v0, p0);
        q0 = fmaf(w3b[j],     v0, q0);
        p1 = fmaf(w3a[j + 1], v1, p1);
        q1 = fmaf(w3b[j + 1], v1, q1);
    }
    F2 r;
    r.a = b3a + (p0 + p1);
    r.b = b3b + (q0 + q1);
    return r;
}

__global__ void ode_zero_kernel() { g_nsum = 0; }

__global__ void __launch_bounds__(NTHR) ode_kernel(
    const float* __restrict__ x0s,
    const float* __restrict__ W1, const float* __restrict__ b1,
    const float* __restrict__ W2, const float* __restrict__ b2,
    const float* __restrict__ W3, const float* __restrict__ b3,
    const int*   __restrict__ Tptr,
    float* __restrict__ out)
{
    const int lane = threadIdx.x & 31;
    const int w    = threadIdx.x >> 5;
    const int traj = blockIdx.x * WPB + w;

    // Load weights into registers (once; cost amortized over the whole solve).
    float w1r[ND], w2r[NH], w3ar[NH], w3br[NH];
#pragma unroll
    for (int j = 0; j < ND; j++) w1r[j] = __ldg(W1 + lane * ND + j);
#pragma unroll
    for (int j = 0; j < NH; j++) w2r[j] = __ldg(W2 + lane * NH + j);
#pragma unroll
    for (int j = 0; j < NH; j++) w3ar[j] = __ldg(W3 + lane * NH + j);
#pragma unroll
    for (int j = 0; j < NH; j++) w3br[j] = __ldg(W3 + (lane + 32) * NH + j);
    const float b1r = __ldg(b1 + lane);
    const float b2r = __ldg(b2 + lane);
    const float b3a = __ldg(b3 + lane);
    const float b3b = __ldg(b3 + lane + 32);

    float y0 = x0s[traj * ND + lane];
    float y1 = x0s[traj * ND + 32 + lane];
    float* otraj = out + (size_t)traj * (NTRAJ * ND);
    otraj[lane]      = y0;
    otraj[32 + lane] = y1;

    const float delta = (float)(*Tptr) * 0.1f;
    float t  = 0.0f;
    float dt = DT0;
    int   n  = 0;

    // FSAL: k1 = f(y); stays valid whenever y is unchanged (reject / interval
    // boundary) and equals the previous k7 after an accepted step.
    float k1a, k1b;
    {
        F2 k = mlp(w1r, w2r, w3ar, w3br, b1r, b2r, b3a, b3b, y0, y1);
        k1a = k.a; k1b = k.b;
    }

    for (int s = 1; s < NTRAJ; s++) {
        float t_target = delta * (float)s;
        for (int it = 0; it < MAXI; it++) {
            float remaining = t_target - t;
            if (remaining <= 1e-12f) break;
            float h = fminf(dt, fmaxf(remaining, 0.0f));

            F2 k2 = mlp(w1r, w2r, w3ar, w3br, b1r, b2r, b3a, b3b,
                        y0 + h * (A21 * k1a),
                        y1 + h * (A21 * k1b));
            F2 k3 = mlp(w1r, w2r, w3ar, w3br, b1r, b2r, b3a, b3b,
                        y0 + h * (A31 * k1a + A32 * k2.a),
                        y1 + h * (A31 * k1b + A32 * k2.b));
            F2 k4 = mlp(w1r, w2r, w3ar, w3br, b1r, b2r, b3a, b3b,
                        y0 + h * (A41 * k1a + A42 * k2.a + A43 * k3.a),
                        y1 + h * (A41 * k1b + A42 * k2.b + A43 * k3.b));
            F2 k5 = mlp(w1r, w2r, w3ar, w3br, b1r, b2r, b3a, b3b,
                        y0 + h * (A51 * k1a + A52 * k2.a + A53 * k3.a + A54 * k4.a),
                        y1 + h * (A51 * k1b + A52 * k2.b + A53 * k3.b + A54 * k4.b));
            F2 k6 = mlp(w1r, w2r, w3ar, w3br, b1r, b2r, b3a, b3b,
                        y0 + h * (A61 * k1a + A62 * k2.a + A63 * k3.a + A64 * k4.a + A65 * k5.a),
                        y1 + h * (A61 * k1b + A62 * k2.b + A63 * k3.b + A64 * k4.b + A65 * k5.b));

            float y5a = y0 + h * (CB1 * k1a + CB2 * k2.a + CB3 * k3.a +
                                  CB4 * k4.a + CB5 * k5.a + CB6 * k6.a);
            float y5b = y1 + h * (CB1 * k1b + CB2 * k2.b + CB3 * k3.b +
                                  CB4 * k4.b + CB5 * k5.b + CB6 * k6.b);

            F2 k7 = mlp(w1r, w2r, w3ar, w3br, b1r, b2r, b3a, b3b, y5a, y5b);

            float ea = h * (CE1 * k1a + CE2 * k2.a + CE3 * k3.a + CE4 * k4.a +
                            CE5 * k5.a + CE6 * k6.a + CE7 * k7.a);
            float eb = h * (CE1 * k1b + CE2 * k2.b + CE3 * k3.b + CE4 * k4.b +
                            CE5 * k5.b + CE6 * k6.b + CE7 * k7.b);

            float sa  = ATOL + RTOL * fmaxf(fabsf(y0), fabsf(y5a));
            float sb_ = ATOL + RTOL * fmaxf(fabsf(y1), fabsf(y5b));
            float ra = ea / sa, rb = eb / sb_;
            float ss = ra * ra + rb * rb;
#pragma unroll
            for (int off = 16; off > 0; off >>= 1)
                ss += __shfl_xor_sync(FULLM, ss, off);
            float enorm = fmaxf(sqrtf(ss * (1.0f / 64.0f)), 1e-10f);

            bool  accept = (enorm <= 1.0f);
            float fac = fminf(fmaxf(0.9f * powf(enorm, -0.2f), 0.1f), 5.0f);
            if (accept) {
                t = t + h; y0 = y5a; y1 = y5b;
                k1a = k7.a; k1b = k7.b;     // FSAL
            }
            dt = fmaxf(h * fac, 1e-8f);
            n += 1;
        }
        otraj[s * ND + lane]      = y0;
        otraj[s * ND + 32 + lane] = y1;
    }

    if (lane == 0) atomicAdd(&g_nsum, n);
}

__global__ void ode_write_n(float* __restrict__ out, int idx) {
    out[idx] = (float)g_nsum;
}

extern "C" void kernel_launch(void* const* d_in, const int* in_sizes, int n_in,
                              void* d_out, int out_size) {
    const float* x0s = (const float*)d_in[0];
    const float* W1  = (const float*)d_in[1];
    const float* b1  = (const float*)d_in[2];
    const float* W2  = (const float*)d_in[3];
    const float* b2  = (const float*)d_in[4];
    const float* W3  = (const float*)d_in[5];
    const float* b3  = (const float*)d_in[6];
    const int*   T   = (const int*)d_in[7];
    float* out = (float*)d_out;

    ode_zero_kernel<<<1, 1>>>();
    ode_kernel<<<NBLK, NTHR>>>(x0s, W1, b1, W2, b2, W3, b3, T, out);
    if (out_size > OUT_TRAJ)
        ode_write_n<<<1, 1>>>(out, OUT_TRAJ);
}

// round 8
// speedup vs baseline: 1.2061x; 1.0924x over previous
#include <cuda_runtime.h>

// NeuralODE adaptive Tsit5. One warp per trajectory; weights register-resident
// (160 regs/lane); stage vectors broadcast via shared-memory LDS.128 (uniform
// address = 4 values per warp-op, replacing 4 SHFLs). FSAL: k1 = previous k7.
// Single kernel launch: Σn reduced via last-block pattern with self-resetting
// device counters (graph-safe, deterministic).

#define NB    4096
#define ND    64
#define NH    32
#define NTRAJ 11
#define MAXI  64
#define NTHR  128
#define WPB   (NTHR / 32)
#define NBLK  (NB / WPB)
#define OUT_TRAJ (NB * NTRAJ * ND)
#define FULLM 0xffffffffu

#define A21 0.161f
#define A31 (-0.008480655492356989f)
#define A32 0.335480655492357f
#define A41 2.8971530571054935f
#define A42 (-6.359448489975075f)
#define A43 4.3622954328695815f
#define A51 5.325864828439257f
#define A52 (-11.748883564062828f)
#define A53 7.4955393428898365f
#define A54 (-0.09249506636175525f)
#define A61 5.86145544294642f
#define A62 (-12.92096931784711f)
#define A63 8.159367898576159f
#define A64 (-0.071584973281401f)
#define A65 (-0.028269050394068383f)
#define CB1 0.09646076681806523f
#define CB2 0.01f
#define CB3 0.4798896504144996f
#define CB4 1.379008574103742f
#define CB5 (-3.290069515436081f)
#define CB6 2.324710524099774f
#define CE1 (-0.00178001105222577714f)
#define CE2 (-0.0008164344596567469f)
#define CE3 0.007880878010261995f
#define CE4 (-0.1447110071732629f)
#define CE5 0.5823571654525552f
#define CE6 (-0.45808210592918697f)
#define CE7 0.015151515151515152f

#define RTOL 1e-3f
#define ATOL 1e-6f
#define DT0  1e-3f

__device__ int g_nsum  = 0;   // self-resetting accumulators (last-block pattern)
__device__ int g_count = 0;

__device__ __forceinline__ float softplus_f(float x) {
    return fmaxf(x, 0.0f) + log1pf(expf(-fabsf(x)));
}

struct F2 { float a, b; };

// MLP eval. Weights in registers; stage/h vectors broadcast via smem LDS.128.
// ysw: 64-float per-warp buffer (16B aligned); hsw: 32-float per-warp buffer.
__device__ __forceinline__ F2 mlp(
    const float (&w1)[ND], const float (&w2)[NH],
    const float (&w3a)[NH], const float (&w3b)[NH],
    float b1r, float b2r, float b3a, float b3b,
    float* __restrict__ ysw, float* __restrict__ hsw,
    int lane, float a0, float a1)
{
    ysw[lane]      = a0;
    ysw[lane + 32] = a1;
    __syncwarp();

    // layer 1: 64-input dot; 16 broadcast LDS.128 feed 64 FMAs
    float s0 = 0.f, s1 = 0.f, s2 = 0.f, s3 = 0.f;
#pragma unroll
    for (int j = 0; j < 16; j++) {
        float4 v = *reinterpret_cast<const float4*>(ysw + j * 4);
        s0 = fmaf(w1[j * 4 + 0], v.x, s0);
        s1 = fmaf(w1[j * 4 + 1], v.y, s1);
        s2 = fmaf(w1[j * 4 + 2], v.z, s2);
        s3 = fmaf(w1[j * 4 + 3], v.w, s3);
    }
    float h1 = softplus_f(b1r + ((s0 + s1) + (s2 + s3)));
    __syncwarp();
    hsw[lane] = h1;
    __syncwarp();

    // layer 2: 32-input dot; 8 broadcast LDS.128
    float t0 = 0.f, t1 = 0.f, t2 = 0.f, t3 = 0.f;
#pragma unroll
    for (int j = 0; j < 8; j++) {
        float4 v = *reinterpret_cast<const float4*>(hsw + j * 4);
        t0 = fmaf(w2[j * 4 + 0], v.x, t0);
        t1 = fmaf(w2[j * 4 + 1], v.y, t1);
        t2 = fmaf(w2[j * 4 + 2], v.z, t2);
        t3 = fmaf(w2[j * 4 + 3], v.w, t3);
    }
    float h2 = softplus_f(b2r + ((t0 + t1) + (t2 + t3)));
    __syncwarp();
    hsw[lane] = h2;
    __syncwarp();

    // layer 3: two 32-input dots; 8 broadcast LDS.128 feed 64 FMAs
    float p0 = 0.f, p1 = 0.f, q0 = 0.f, q1 = 0.f;
#pragma unroll
    for (int j = 0; j < 8; j++) {
        float4 v = *reinterpret_cast<const float4*>(hsw + j * 4);
        p0 = fmaf(w3a[j * 4 + 0], v.x, p0);
        q0 = fmaf(w3b[j * 4 + 0], v.x, q0);
        p1 = fmaf(w3a[j * 4 + 1], v.y, p1);
        q1 = fmaf(w3b[j * 4 + 1], v.y, q1);
        p0 = fmaf(w3a[j * 4 + 2], v.z, p0);
        q0 = fmaf(w3b[j * 4 + 2], v.z, q0);
        p1 = fmaf(w3a[j * 4 + 3], v.w, p1);
        q1 = fmaf(w3b[j * 4 + 3], v.w, q1);
    }
    __syncwarp();   // protect hsw before next eval's overwrite
    F2 r;
    r.a = b3a + (p0 + p1);
    r.b = b3b + (q0 + q1);
    return r;
}

__global__ void __launch_bounds__(NTHR) ode_kernel(
    const float* __restrict__ x0s,
    const float* __restrict__ W1, const float* __restrict__ b1,
    const float* __restrict__ W2, const float* __restrict__ b2,
    const float* __restrict__ W3, const float* __restrict__ b3,
    const int*   __restrict__ Tptr,
    float* __restrict__ out, int out_size)
{
    __shared__ __align__(16) float ys[WPB][ND];
    __shared__ __align__(16) float hs[WPB][NH];

    const int lane = threadIdx.x & 31;
    const int w    = threadIdx.x >> 5;
    const int traj = blockIdx.x * WPB + w;
    float* ysw = ys[w];
    float* hsw = hs[w];

    float w1r[ND], w2r[NH], w3ar[NH], w3br[NH];
#pragma unroll
    for (int j = 0; j < ND; j++) w1r[j] = __ldg(W1 + lane * ND + j);
#pragma unroll
    for (int j = 0; j < NH; j++) w2r[j] = __ldg(W2 + lane * NH + j);
#pragma unroll
    for (int j = 0; j < NH; j++) w3ar[j] = __ldg(W3 + lane * NH + j);
#pragma unroll
    for (int j = 0; j < NH; j++) w3br[j] = __ldg(W3 + (lane + 32) * NH + j);
    const float b1r = __ldg(b1 + lane);
    const float b2r = __ldg(b2 + lane);
    const float b3a = __ldg(b3 + lane);
    const float b3b = __ldg(b3 + lane + 32);

    float y0 = x0s[traj * ND + lane];
    float y1 = x0s[traj * ND + 32 + lane];
    float* otraj = out + (size_t)traj * (NTRAJ * ND);
    otraj[lane]      = y0;
    otraj[32 + lane] = y1;

    const float delta = (float)(*Tptr) * 0.1f;
    float t  = 0.0f;
    float dt = DT0;
    int   n  = 0;

    // FSAL seed
    float k1a, k1b;
    {
        F2 k = mlp(w1r, w2r, w3ar, w3br, b1r, b2r, b3a, b3b, ysw, hsw, lane, y0, y1);
        k1a = k.a; k1b = k.b;
    }

    for (int s = 1; s < NTRAJ; s++) {
        float t_target = delta * (float)s;
        for (int it = 0; it < MAXI; it++) {
            float remaining = t_target - t;
            if (remaining <= 1e-12f) break;
            float h = fminf(dt, fmaxf(remaining, 0.0f));

            F2 k2 = mlp(w1r, w2r, w3ar, w3br, b1r, b2r, b3a, b3b, ysw, hsw, lane,
                        y0 + h * (A21 * k1a),
                        y1 + h * (A21 * k1b));
            F2 k3 = mlp(w1r, w2r, w3ar, w3br, b1r, b2r, b3a, b3b, ysw, hsw, lane,
                        y0 + h * (A31 * k1a + A32 * k2.a),
                        y1 + h * (A31 * k1b + A32 * k2.b));
            F2 k4 = mlp(w1r, w2r, w3ar, w3br, b1r, b2r, b3a, b3b, ysw, hsw, lane,
                        y0 + h * (A41 * k1a + A42 * k2.a + A43 * k3.a),
                        y1 + h * (A41 * k1b + A42 * k2.b + A43 * k3.b));
            F2 k5 = mlp(w1r, w2r, w3ar, w3br, b1r, b2r, b3a, b3b, ysw, hsw, lane,
                        y0 + h * (A51 * k1a + A52 * k2.a + A53 * k3.a + A54 * k4.a),
                        y1 + h * (A51 * k1b + A52 * k2.b + A53 * k3.b + A54 * k4.b));
            F2 k6 = mlp(w1r, w2r, w3ar, w3br, b1r, b2r, b3a, b3b, ysw, hsw, lane,
                        y0 + h * (A61 * k1a + A62 * k2.a + A63 * k3.a + A64 * k4.a + A65 * k5.a),
                        y1 + h * (A61 * k1b + A62 * k2.b + A63 * k3.b + A64 * k4.b + A65 * k5.b));

            float y5a = y0 + h * (CB1 * k1a + CB2 * k2.a + CB3 * k3.a +
                                  CB4 * k4.a + CB5 * k5.a + CB6 * k6.a);
            float y5b = y1 + h * (CB1 * k1b + CB2 * k2.b + CB3 * k3.b +
                                  CB4 * k4.b + CB5 * k5.b + CB6 * k6.b);

            F2 k7 = mlp(w1r, w2r, w3ar, w3br, b1r, b2r, b3a, b3b, ysw, hsw, lane, y5a, y5b);

            float ea = h * (CE1 * k1a + CE2 * k2.a + CE3 * k3.a + CE4 * k4.a +
                            CE5 * k5.a + CE6 * k6.a + CE7 * k7.a);
            float eb = h * (CE1 * k1b + CE2 * k2.b + CE3 * k3.b + CE4 * k4.b +
                            CE5 * k5.b + CE6 * k6.b + CE7 * k7.b);

            float sa  = ATOL + RTOL * fmaxf(fabsf(y0), fabsf(y5a));
            float sb_ = ATOL + RTOL * fmaxf(fabsf(y1), fabsf(y5b));
            float ra = ea / sa, rb = eb / sb_;
            float ss = ra * ra + rb * rb;
#pragma unroll
            for (int off = 16; off > 0; off >>= 1)
                ss += __shfl_xor_sync(FULLM, ss, off);
            float enorm = fmaxf(sqrtf(ss * (1.0f / 64.0f)), 1e-10f);

            bool  accept = (enorm <= 1.0f);
            float fac = fminf(fmaxf(0.9f * powf(enorm, -0.2f), 0.1f), 5.0f);
            if (accept) {
                t = t + h; y0 = y5a; y1 = y5b;
                k1a = k7.a; k1b = k7.b;     // FSAL
            }
            dt = fmaxf(h * fac, 1e-8f);
            n += 1;
        }
        otraj[s * ND + lane]      = y0;
        otraj[s * ND + 32 + lane] = y1;
    }

    // Σn reduction: warp leaders add; last finished block writes + resets.
    if (lane == 0) atomicAdd(&g_nsum, n);
    __syncthreads();
    if (threadIdx.x == 0) {
        __threadfence();
        int arrived = atomicAdd(&g_count, 1);
        if (arrived == NBLK - 1) {
            int total = atomicAdd(&g_nsum, 0);
            if (out_size > OUT_TRAJ)
                out[OUT_TRAJ] = (float)total;
            // self-reset for next graph replay
            atomicExch(&g_nsum, 0);
            atomicExch(&g_count, 0);
        }
    }
}

extern "C" void kernel_launch(void* const* d_in, const int* in_sizes, int n_in,
                              void* d_out, int out_size) {
    const float* x0s = (const float*)d_in[0];
    const float* W1  = (const float*)d_in[1];
    const float* b1  = (const float*)d_in[2];
    const float* W2  = (const float*)d_in[3];
    const float* b2  = (const float*)d_in[4];
    const float* W3  = (const float*)d_in[5];
    const float* b3  = (const float*)d_in[6];
    const int*   T   = (const int*)d_in[7];
    float* out = (float*)d_out;

    ode_kernel<<<NBLK, NTHR>>>(x0s, W1, b1, W2, b2, W3, b3, T, out, out_size);
}

// round 9
// speedup vs baseline: 1.3077x; 1.0843x over previous
#include <cuda_runtime.h>

// NeuralODE adaptive Tsit5, one warp per trajectory. Weights register-resident,
// PACKED as f32x2 (fma.rn.f32x2 / FFMA2: 2 MACs per issued op, sm_103a only).
// Stage vectors packed into f32x2 pairs once per eval via neighbor-lane SHFL +
// predicated STS.64, then broadcast-read as 16B uniform LDS. FSAL k1=prev k7.
// Single launch; Σn via last-block reduction with self-resetting counters.

#define NB    4096
#define ND    64
#define NH    32
#define NTRAJ 11
#define MAXI  64
#define NTHR  128
#define WPB   (NTHR / 32)
#define NBLK  (NB / WPB)
#define OUT_TRAJ (NB * NTRAJ * ND)
#define FULLM 0xffffffffu

#define A21 0.161f
#define A31 (-0.008480655492356989f)
#define A32 0.335480655492357f
#define A41 2.8971530571054935f
#define A42 (-6.359448489975075f)
#define A43 4.3622954328695815f
#define A51 5.325864828439257f
#define A52 (-11.748883564062828f)
#define A53 7.4955393428898365f
#define A54 (-0.09249506636175525f)
#define A61 5.86145544294642f
#define A62 (-12.92096931784711f)
#define A63 8.159367898576159f
#define A64 (-0.071584973281401f)
#define A65 (-0.028269050394068383f)
#define CB1 0.09646076681806523f
#define CB2 0.01f
#define CB3 0.4798896504144996f
#define CB4 1.379008574103742f
#define CB5 (-3.290069515436081f)
#define CB6 2.324710524099774f
#define CE1 (-0.00178001105222577714f)
#define CE2 (-0.0008164344596567469f)
#define CE3 0.007880878010261995f
#define CE4 (-0.1447110071732629f)
#define CE5 0.5823571654525552f
#define CE6 (-0.45808210592918697f)
#define CE7 0.015151515151515152f

#define RTOL 1e-3f
#define ATOL 1e-6f
#define DT0  1e-3f

typedef unsigned long long u64t;

__device__ int g_nsum  = 0;
__device__ int g_count = 0;

__device__ __forceinline__ float softplus_f(float x) {
    return fmaxf(x, 0.0f) + log1pf(expf(-fabsf(x)));
}

__device__ __forceinline__ u64t pack2(float lo, float hi) {
    u64t r; asm("mov.b64 %0, {%1, %2};" : "=l"(r) : "f"(lo), "f"(hi)); return r;
}
__device__ __forceinline__ u64t ffma2(u64t a, u64t b, u64t c) {
    u64t r; asm("fma.rn.f32x2 %0, %1, %2, %3;" : "=l"(r) : "l"(a), "l"(b), "l"(c)); return r;
}
__device__ __forceinline__ u64t add2(u64t a, u64t b) {
    u64t r; asm("add.rn.f32x2 %0, %1, %2;" : "=l"(r) : "l"(a), "l"(b)); return r;
}
__device__ __forceinline__ float hsum2(u64t v) {
    float lo, hi; asm("mov.b64 {%0, %1}, %2;" : "=f"(lo), "=f"(hi) : "l"(v));
    return lo + hi;
}

struct F2 { float a, b; };

// MLP eval. Weights as packed f32x2 in registers; stage pairs packed in smem.
// ysp: 32 u64 per warp (y pairs), hsp: 16 u64 per warp (hidden pairs).
__device__ __forceinline__ F2 mlp(
    const u64t (&w1p)[32], const u64t (&w2p)[16],
    const u64t (&w3ap)[16], const u64t (&w3bp)[16],
    float b1r, float b2r, float b3a, float b3b,
    u64t* __restrict__ ysp, u64t* __restrict__ hsp,
    int lane, float a0, float a1)
{
    // Pack stage pairs: even lane 2p stores (y[2p],y[2p+1]) and (y[32+2p],y[33+2p]).
    float a0n = __shfl_down_sync(FULLM, a0, 1);
    float a1n = __shfl_down_sync(FULLM, a1, 1);
    if (!(lane & 1)) {
        int p = lane >> 1;
        ysp[p]      = pack2(a0, a0n);
        ysp[16 + p] = pack2(a1, a1n);
    }
    __syncwarp();

    // layer 1: 32 FFMA2 over 4 packed accumulators; 16B broadcast loads
    u64t s0 = 0, s1 = 0, s2 = 0, s3 = 0;
#pragma unroll
    for (int j = 0; j < 32; j += 4) {
        ulonglong2 va = *reinterpret_cast<const ulonglong2*>(ysp + j);
        ulonglong2 vb = *reinterpret_cast<const ulonglong2*>(ysp + j + 2);
        s0 = ffma2(w1p[j],     va.x, s0);
        s1 = ffma2(w1p[j + 1], va.y, s1);
        s2 = ffma2(w1p[j + 2], vb.x, s2);
        s3 = ffma2(w1p[j + 3], vb.y, s3);
    }
    float h1 = softplus_f(b1r + hsum2(add2(add2(s0, s1), add2(s2, s3))));

    // pack hidden pairs
    float h1n = __shfl_down_sync(FULLM, h1, 1);
    __syncwarp();
    if (!(lane & 1)) hsp[lane >> 1] = pack2(h1, h1n);
    __syncwarp();

    // layer 2: 16 FFMA2
    u64t t0 = 0, t1 = 0, t2 = 0, t3 = 0;
#pragma unroll
    for (int j = 0; j < 16; j += 4) {
        ulonglong2 va = *reinterpret_cast<const ulonglong2*>(hsp + j);
        ulonglong2 vb = *reinterpret_cast<const ulonglong2*>(hsp + j + 2);
        t0 = ffma2(w2p[j],     va.x, t0);
        t1 = ffma2(w2p[j + 1], va.y, t1);
        t2 = ffma2(w2p[j + 2], vb.x, t2);
        t3 = ffma2(w2p[j + 3], vb.y, t3);
    }
    float h2 = softplus_f(b2r + hsum2(add2(add2(t0, t1), add2(t2, t3))));

    float h2n = __shfl_down_sync(FULLM, h2, 1);
    __syncwarp();
    if (!(lane & 1)) hsp[lane >> 1] = pack2(h2, h2n);
    __syncwarp();

    // layer 3: two outputs per lane, 32 FFMA2 sharing broadcasts
    u64t p0 = 0, p1 = 0, q0 = 0, q1 = 0;
#pragma unroll
    for (int j = 0; j < 16; j += 4) {
        ulonglong2 va = *reinterpret_cast<const ulonglong2*>(hsp + j);
        ulonglong2 vb = *reinterpret_cast<const ulonglong2*>(hsp + j + 2);
        p0 = ffma2(w3ap[j],     va.x, p0);  q0 = ffma2(w3bp[j],     va.x, q0);
        p1 = ffma2(w3ap[j + 1], va.y, p1);  q1 = ffma2(w3bp[j + 1], va.y, q1);
        p0 = ffma2(w3ap[j + 2], vb.x, p0);  q0 = ffma2(w3bp[j + 2], vb.x, q0);
        p1 = ffma2(w3ap[j + 3], vb.y, p1);  q1 = ffma2(w3bp[j + 3], vb.y, q1);
    }
    __syncwarp();   // all reads of hsp/ysp done before next eval overwrites
    F2 r;
    r.a = b3a + hsum2(add2(p0, p1));
    r.b = b3b + hsum2(add2(q0, q1));
    return r;
}

__global__ void __launch_bounds__(NTHR) ode_kernel(
    const float* __restrict__ x0s,
    const float* __restrict__ W1, const float* __restrict__ b1,
    const float* __restrict__ W2, const float* __restrict__ b2,
    const float* __restrict__ W3, const float* __restrict__ b3,
    const int*   __restrict__ Tptr,
    float* __restrict__ out, int out_size)
{
    __shared__ __align__(16) u64t ys[WPB][32];
    __shared__ __align__(16) u64t hs[WPB][16];

    const int lane = threadIdx.x & 31;
    const int w    = threadIdx.x >> 5;
    const int traj = blockIdx.x * WPB + w;
    u64t* ysp = ys[w];
    u64t* hsp = hs[w];

    // Packed weight registers: pair index p holds columns (2p, 2p+1).
    u64t w1p[32], w2p[16], w3ap[16], w3bp[16];
#pragma unroll
    for (int p = 0; p < 32; p++)
        w1p[p] = pack2(__ldg(W1 + lane * ND + 2 * p), __ldg(W1 + lane * ND + 2 * p + 1));
#pragma unroll
    for (int p = 0; p < 16; p++)
        w2p[p] = pack2(__ldg(W2 + lane * NH + 2 * p), __ldg(W2 + lane * NH + 2 * p + 1));
#pragma unroll
    for (int p = 0; p < 16; p++)
        w3ap[p] = pack2(__ldg(W3 + lane * NH + 2 * p), __ldg(W3 + lane * NH + 2 * p + 1));
#pragma unroll
    for (int p = 0; p < 16; p++)
        w3bp[p] = pack2(__ldg(W3 + (lane + 32) * NH + 2 * p), __ldg(W3 + (lane + 32) * NH + 2 * p + 1));
    const float b1r = __ldg(b1 + lane);
    const float b2r = __ldg(b2 + lane);
    const float b3a = __ldg(b3 + lane);
    const float b3b = __ldg(b3 + lane + 32);

    float y0 = x0s[traj * ND + lane];
    float y1 = x0s[traj * ND + 32 + lane];
    float* otraj = out + (size_t)traj * (NTRAJ * ND);
    otraj[lane]      = y0;
    otraj[32 + lane] = y1;

    const float delta = (float)(*Tptr) * 0.1f;
    float t  = 0.0f;
    float dt = DT0;
    int   n  = 0;

    float k1a, k1b;
    {
        F2 k = mlp(w1p, w2p, w3ap, w3bp, b1r, b2r, b3a, b3b, ysp, hsp, lane, y0, y1);
        k1a = k.a; k1b = k.b;
    }

    for (int s = 1; s < NTRAJ; s++) {
        float t_target = delta * (float)s;
        for (int it = 0; it < MAXI; it++) {
            float remaining = t_target - t;
            if (remaining <= 1e-12f) break;
            float h = fminf(dt, fmaxf(remaining, 0.0f));

            F2 k2 = mlp(w1p, w2p, w3ap, w3bp, b1r, b2r, b3a, b3b, ysp, hsp, lane,
                        y0 + h * (A21 * k1a),
                        y1 + h * (A21 * k1b));
            F2 k3 = mlp(w1p, w2p, w3ap, w3bp, b1r, b2r, b3a, b3b, ysp, hsp, lane,
                        y0 + h * (A31 * k1a + A32 * k2.a),
                        y1 + h * (A31 * k1b + A32 * k2.b));
            F2 k4 = mlp(w1p, w2p, w3ap, w3bp, b1r, b2r, b3a, b3b, ysp, hsp, lane,
                        y0 + h * (A41 * k1a + A42 * k2.a + A43 * k3.a),
                        y1 + h * (A41 * k1b + A42 * k2.b + A43 * k3.b));
            F2 k5 = mlp(w1p, w2p, w3ap, w3bp, b1r, b2r, b3a, b3b, ysp, hsp, lane,
                        y0 + h * (A51 * k1a + A52 * k2.a + A53 * k3.a + A54 * k4.a),
                        y1 + h * (A51 * k1b + A52 * k2.b + A53 * k3.b + A54 * k4.b));
            F2 k6 = mlp(w1p, w2p, w3ap, w3bp, b1r, b2r, b3a, b3b, ysp, hsp, lane,
                        y0 + h * (A61 * k1a + A62 * k2.a + A63 * k3.a + A64 * k4.a + A65 * k5.a),
                        y1 + h * (A61 * k1b + A62 * k2.b + A63 * k3.b + A64 * k4.b + A65 * k5.b));

            float y5a = y0 + h * (CB1 * k1a + CB2 * k2.a + CB3 * k3.a +
                                  CB4 * k4.a + CB5 * k5.a + CB6 * k6.a);
            float y5b = y1 + h * (CB1 * k1b + CB2 * k2.b + CB3 * k3.b +
                                  CB4 * k4.b + CB5 * k5.b + CB6 * k6.b);

            F2 k7 = mlp(w1p, w2p, w3ap, w3bp, b1r, b2r, b3a, b3b, ysp, hsp, lane, y5a, y5b);

            float ea = h * (CE1 * k1a + CE2 * k2.a + CE3 * k3.a + CE4 * k4.a +
                            CE5 * k5.a + CE6 * k6.a + CE7 * k7.a);
            float eb = h * (CE1 * k1b + CE2 * k2.b + CE3 * k3.b + CE4 * k4.b +
                            CE5 * k5.b + CE6 * k6.b + CE7 * k7.b);

            float sa  = ATOL + RTOL * fmaxf(fabsf(y0), fabsf(y5a));
            float sb_ = ATOL + RTOL * fmaxf(fabsf(y1), fabsf(y5b));
            float ra = ea / sa, rb = eb / sb_;
            float ss = ra * ra + rb * rb;
#pragma unroll
            for (int off = 16; off > 0; off >>= 1)
                ss += __shfl_xor_sync(FULLM, ss, off);
            float enorm = fmaxf(sqrtf(ss * (1.0f / 64.0f)), 1e-10f);

            bool  accept = (enorm <= 1.0f);
            float fac = fminf(fmaxf(0.9f * powf(enorm, -0.2f), 0.1f), 5.0f);
            if (accept) {
                t = t + h; y0 = y5a; y1 = y5b;
                k1a = k7.a; k1b = k7.b;     // FSAL
            }
            dt = fmaxf(h * fac, 1e-8f);
            n += 1;
        }
        otraj[s * ND + lane]      = y0;
        otraj[s * ND + 32 + lane] = y1;
    }

    if (lane == 0) atomicAdd(&g_nsum, n);
    __syncthreads();
    if (threadIdx.x == 0) {
        __threadfence();
        int arrived = atomicAdd(&g_count, 1);
        if (arrived == NBLK - 1) {
            int total = atomicAdd(&g_nsum, 0);
            if (out_size > OUT_TRAJ)
                out[OUT_TRAJ] = (float)total;
            atomicExch(&g_nsum, 0);
            atomicExch(&g_count, 0);
        }
    }
}

extern "C" void kernel_launch(void* const* d_in, const int* in_sizes, int n_in,
                              void* d_out, int out_size) {
    const float* x0s = (const float*)d_in[0];
    const float* W1  = (const float*)d_in[1];
    const float* b1  = (const float*)d_in[2];
    const float* W2  = (const float*)d_in[3];
    const float* b2  = (const float*)d_in[4];
    const float* W3  = (const float*)d_in[5];
    const float* b3  = (const float*)d_in[6];
    const int*   T   = (const int*)d_in[7];
    float* out = (float*)d_out;

    ode_kernel<<<NBLK, NTHR>>>(x0s, W1, b1, W2, b2, W3, b3, T, out, out_size);
}

// round 15
// speedup vs baseline: 1.4646x; 1.1200x over previous
#include <cuda_runtime.h>

// NeuralODE adaptive Tsit5, one warp per trajectory. f32x2-packed weights in
// registers (FFMA2), broadcast stage pairs via smem, FSAL, early exit.
// R14: fast transcendentals (__expf/__logf softplus, __powf/__fdividef
// controller); warp reduction via SHFL.BFLY tree (redux.f32 not on sm_103a).

#define NB    4096
#define ND    64
#define NH    32
#define NTRAJ 11
#define MAXI  64
#define NTHR  128
#define WPB   (NTHR / 32)
#define NBLK  (NB / WPB)
#define OUT_TRAJ (NB * NTRAJ * ND)
#define FULLM 0xffffffffu

#define A21 0.161f
#define A31 (-0.008480655492356989f)
#define A32 0.335480655492357f
#define A41 2.8971530571054935f
#define A42 (-6.359448489975075f)
#define A43 4.3622954328695815f
#define A51 5.325864828439257f
#define A52 (-11.748883564062828f)
#define A53 7.4955393428898365f
#define A54 (-0.09249506636175525f)
#define A61 5.86145544294642f
#define A62 (-12.92096931784711f)
#define A63 8.159367898576159f
#define A64 (-0.071584973281401f)
#define A65 (-0.028269050394068383f)
#define CB1 0.09646076681806523f
#define CB2 0.01f
#define CB3 0.4798896504144996f
#define CB4 1.379008574103742f
#define CB5 (-3.290069515436081f)
#define CB6 2.324710524099774f
#define CE1 (-0.00178001105222577714f)
#define CE2 (-0.0008164344596567469f)
#define CE3 0.007880878010261995f
#define CE4 (-0.1447110071732629f)
#define CE5 0.5823571654525552f
#define CE6 (-0.45808210592918697f)
#define CE7 0.015151515151515152f

#define RTOL 1e-3f
#define ATOL 1e-6f
#define DT0  1e-3f

typedef unsigned long long u64t;

__device__ int g_nsum  = 0;
__device__ int g_count = 0;

// Fast softplus: max(x,0) + log(1 + exp(-|x|)) with MUFU intrinsics.
// Abs error ~1e-7; relative error negligible where the log term is small.
__device__ __forceinline__ float softplus_f(float x) {
    return fmaxf(x, 0.0f) + __logf(1.0f + __expf(-fabsf(x)));
}

__device__ __forceinline__ u64t pack2(float lo, float hi) {
    u64t r; asm("mov.b64 %0, {%1, %2};" : "=l"(r) : "f"(lo), "f"(hi)); return r;
}
__device__ __forceinline__ u64t ffma2(u64t a, u64t b, u64t c) {
    u64t r; asm("fma.rn.f32x2 %0, %1, %2, %3;" : "=l"(r) : "l"(a), "l"(b), "l"(c)); return r;
}
__device__ __forceinline__ u64t add2(u64t a, u64t b) {
    u64t r; asm("add.rn.f32x2 %0, %1, %2;" : "=l"(r) : "l"(a), "l"(b)); return r;
}
__device__ __forceinline__ float hsum2(u64t v) {
    float lo, hi; asm("mov.b64 {%0, %1}, %2;" : "=f"(lo), "=f"(hi) : "l"(v));
    return lo + hi;
}

struct F2 { float a, b; };

__device__ __forceinline__ F2 mlp(
    const u64t (&w1p)[32], const u64t (&w2p)[16],
    const u64t (&w3ap)[16], const u64t (&w3bp)[16],
    float b1r, float b2r, float b3a, float b3b,
    u64t* __restrict__ ysp, u64t* __restrict__ hsp,
    int lane, float a0, float a1)
{
    float a0n = __shfl_down_sync(FULLM, a0, 1);
    float a1n = __shfl_down_sync(FULLM, a1, 1);
    if (!(lane & 1)) {
        int p = lane >> 1;
        ysp[p]      = pack2(a0, a0n);
        ysp[16 + p] = pack2(a1, a1n);
    }
    __syncwarp();

    u64t s0 = 0, s1 = 0, s2 = 0, s3 = 0;
#pragma unroll
    for (int j = 0; j < 32; j += 4) {
        ulonglong2 va = *reinterpret_cast<const ulonglong2*>(ysp + j);
        ulonglong2 vb = *reinterpret_cast<const ulonglong2*>(ysp + j + 2);
        s0 = ffma2(w1p[j],     va.x, s0);
        s1 = ffma2(w1p[j + 1], va.y, s1);
        s2 = ffma2(w1p[j + 2], vb.x, s2);
        s3 = ffma2(w1p[j + 3], vb.y, s3);
    }
    float h1 = softplus_f(b1r + hsum2(add2(add2(s0, s1), add2(s2, s3))));

    float h1n = __shfl_down_sync(FULLM, h1, 1);
    __syncwarp();
    if (!(lane & 1)) hsp[lane >> 1] = pack2(h1, h1n);
    __syncwarp();

    u64t t0 = 0, t1 = 0, t2 = 0, t3 = 0;
#pragma unroll
    for (int j = 0; j < 16; j += 4) {
        ulonglong2 va = *reinterpret_cast<const ulonglong2*>(hsp + j);
        ulonglong2 vb = *reinterpret_cast<const ulonglong2*>(hsp + j + 2);
        t0 = ffma2(w2p[j],     va.x, t0);
        t1 = ffma2(w2p[j + 1], va.y, t1);
        t2 = ffma2(w2p[j + 2], vb.x, t2);
        t3 = ffma2(w2p[j + 3], vb.y, t3);
    }
    float h2 = softplus_f(b2r + hsum2(add2(add2(t0, t1), add2(t2, t3))));

    float h2n = __shfl_down_sync(FULLM, h2, 1);
    __syncwarp();
    if (!(lane & 1)) hsp[lane >> 1] = pack2(h2, h2n);
    __syncwarp();

    u64t p0 = 0, p1 = 0, q0 = 0, q1 = 0;
#pragma unroll
    for (int j = 0; j < 16; j += 4) {
        ulonglong2 va = *reinterpret_cast<const ulonglong2*>(hsp + j);
        ulonglong2 vb = *reinterpret_cast<const ulonglong2*>(hsp + j + 2);
        p0 = ffma2(w3ap[j],     va.x, p0);  q0 = ffma2(w3bp[j],     va.x, q0);
        p1 = ffma2(w3ap[j + 1], va.y, p1);  q1 = ffma2(w3bp[j + 1], va.y, q1);
        p0 = ffma2(w3ap[j + 2], vb.x, p0);  q0 = ffma2(w3bp[j + 2], vb.x, q0);
        p1 = ffma2(w3ap[j + 3], vb.y, p1);  q1 = ffma2(w3bp[j + 3], vb.y, q1);
    }
    __syncwarp();
    F2 r;
    r.a = b3a + hsum2(add2(p0, p1));
    r.b = b3b + hsum2(add2(q0, q1));
    return r;
}

__global__ void __launch_bounds__(NTHR) ode_kernel(
    const float* __restrict__ x0s,
    const float* __restrict__ W1, const float* __restrict__ b1,
    const float* __restrict__ W2, const float* __restrict__ b2,
    const float* __restrict__ W3, const float* __restrict__ b3,
    const int*   __restrict__ Tptr,
    float* __restrict__ out, int out_size)
{
    __shared__ __align__(16) u64t ys[WPB][32];
    __shared__ __align__(16) u64t hs[WPB][16];

    const int lane = threadIdx.x & 31;
    const int w    = threadIdx.x >> 5;
    const int traj = blockIdx.x * WPB + w;
    u64t* ysp = ys[w];
    u64t* hsp = hs[w];

    u64t w1p[32], w2p[16], w3ap[16], w3bp[16];
#pragma unroll
    for (int p = 0; p < 32; p++)
        w1p[p] = pack2(__ldg(W1 + lane * ND + 2 * p), __ldg(W1 + lane * ND + 2 * p + 1));
#pragma unroll
    for (int p = 0; p < 16; p++)
        w2p[p] = pack2(__ldg(W2 + lane * NH + 2 * p), __ldg(W2 + lane * NH + 2 * p + 1));
#pragma unroll
    for (int p = 0; p < 16; p++)
        w3ap[p] = pack2(__ldg(W3 + lane * NH + 2 * p), __ldg(W3 + lane * NH + 2 * p + 1));
#pragma unroll
    for (int p = 0; p < 16; p++)
        w3bp[p] = pack2(__ldg(W3 + (lane + 32) * NH + 2 * p), __ldg(W3 + (lane + 32) * NH + 2 * p + 1));
    const float b1r = __ldg(b1 + lane);
    const float b2r = __ldg(b2 + lane);
    const float b3a = __ldg(b3 + lane);
    const float b3b = __ldg(b3 + lane + 32);

    float y0 = x0s[traj * ND + lane];
    float y1 = x0s[traj * ND + 32 + lane];
    float* otraj = out + (size_t)traj * (NTRAJ * ND);
    otraj[lane]      = y0;
    otraj[32 + lane] = y1;

    const float delta = (float)(*Tptr) * 0.1f;
    float t  = 0.0f;
    float dt = DT0;
    int   n  = 0;

    float k1a, k1b;
    {
        F2 k = mlp(w1p, w2p, w3ap, w3bp, b1r, b2r, b3a, b3b, ysp, hsp, lane, y0, y1);
        k1a = k.a; k1b = k.b;
    }

    for (int s = 1; s < NTRAJ; s++) {
        float t_target = delta * (float)s;
        for (int it = 0; it < MAXI; it++) {
            float remaining = t_target - t;
            if (remaining <= 1e-12f) break;
            float h = fminf(dt, fmaxf(remaining, 0.0f));

            F2 k2 = mlp(w1p, w2p, w3ap, w3bp, b1r, b2r, b3a, b3b, ysp, hsp, lane,
                        y0 + h * (A21 * k1a),
                        y1 + h * (A21 * k1b));
            F2 k3 = mlp(w1p, w2p, w3ap, w3bp, b1r, b2r, b3a, b3b, ysp, hsp, lane,
                        y0 + h * (A31 * k1a + A32 * k2.a),
                        y1 + h * (A31 * k1b + A32 * k2.b));
            F2 k4 = mlp(w1p, w2p, w3ap, w3bp, b1r, b2r, b3a, b3b, ysp, hsp, lane,
                        y0 + h * (A41 * k1a + A42 * k2.a + A43 * k3.a),
                        y1 + h * (A41 * k1b + A42 * k2.b + A43 * k3.b));
            F2 k5 = mlp(w1p, w2p, w3ap, w3bp, b1r, b2r, b3a, b3b, ysp, hsp, lane,
                        y0 + h * (A51 * k1a + A52 * k2.a + A53 * k3.a + A54 * k4.a),
                        y1 + h * (A51 * k1b + A52 * k2.b + A53 * k3.b + A54 * k4.b));
            F2 k6 = mlp(w1p, w2p, w3ap, w3bp, b1r, b2r, b3a, b3b, ysp, hsp, lane,
                        y0 + h * (A61 * k1a + A62 * k2.a + A63 * k3.a + A64 * k4.a + A65 * k5.a),
                        y1 + h * (A61 * k1b + A62 * k2.b + A63 * k3.b + A64 * k4.b + A65 * k5.b));

            float y5a = y0 + h * (CB1 * k1a + CB2 * k2.a + CB3 * k3.a +
                                  CB4 * k4.a + CB5 * k5.a + CB6 * k6.a);
            float y5b = y1 + h * (CB1 * k1b + CB2 * k2.b + CB3 * k3.b +
                                  CB4 * k4.b + CB5 * k5.b + CB6 * k6.b);

            F2 k7 = mlp(w1p, w2p, w3ap, w3bp, b1r, b2r, b3a, b3b, ysp, hsp, lane, y5a, y5b);

            float ea = h * (CE1 * k1a + CE2 * k2.a + CE3 * k3.a + CE4 * k4.a +
                            CE5 * k5.a + CE6 * k6.a + CE7 * k7.a);
            float eb = h * (CE1 * k1b + CE2 * k2.b + CE3 * k3.b + CE4 * k4.b +
                            CE5 * k5.b + CE6 * k6.b + CE7 * k7.b);

            float sa  = ATOL + RTOL * fmaxf(fabsf(y0), fabsf(y5a));
            float sb_ = ATOL + RTOL * fmaxf(fabsf(y1), fabsf(y5b));
            float ra = __fdividef(ea, sa), rb = __fdividef(eb, sb_);
            float ss = ra * ra + rb * rb;
#pragma unroll
            for (int off = 16; off > 0; off >>= 1)
                ss += __shfl_xor_sync(FULLM, ss, off);
            float enorm = fmaxf(sqrtf(ss * (1.0f / 64.0f)), 1e-10f);

            bool  accept = (enorm <= 1.0f);
            float fac = fminf(fmaxf(0.9f * __powf(enorm, -0.2f), 0.1f), 5.0f);
            if (accept) {
                t = t + h; y0 = y5a; y1 = y5b;
                k1a = k7.a; k1b = k7.b;     // FSAL
            }
            dt = fmaxf(h * fac, 1e-8f);
            n += 1;
        }
        otraj[s * ND + lane]      = y0;
        otraj[s * ND + 32 + lane] = y1;
    }

    if (lane == 0) atomicAdd(&g_nsum, n);
    __syncthreads();
    if (threadIdx.x == 0) {
        __threadfence();
        int arrived = atomicAdd(&g_count, 1);
        if (arrived == NBLK - 1) {
            int total = atomicAdd(&g_nsum, 0);
            if (out_size > OUT_TRAJ)
                out[OUT_TRAJ] = (float)total;
            atomicExch(&g_nsum, 0);
            atomicExch(&g_count, 0);
        }
    }
}

extern "C" void kernel_launch(void* const* d_in, const int* in_sizes, int n_in,
                              void* d_out, int out_size) {
    const float* x0s = (const float*)d_in[0];
    const float* W1  = (const float*)d_in[1];
    const float* b1  = (const float*)d_in[2];
    const float* W2  = (const float*)d_in[3];
    const float* b2  = (const float*)d_in[4];
    const float* W3  = (const float*)d_in[5];
    const float* b3  = (const float*)d_in[6];
    const int*   T   = (const int*)d_in[7];
    float* out = (float*)d_out;

    ode_kernel<<<NBLK, NTHR>>>(x0s, W1, b1, W2, b2, W3, b3, T, out, out_size);
}